// round 5
// baseline (speedup 1.0000x reference)
#include <cuda_runtime.h>
#include <cstdint>

// Problem constants
#define RES    64
#define C_CH   8
#define NB     64
#define CORE   32
#define POS    16                        // (RES-CORE)/2
#define DIM    (CORE*CORE*CORE*C_CH)     // 262144
#define BATCH  32
#define VOL    (RES*RES*RES)             // 262144
#define BSTRIDE (C_CH*VOL)               // 2097152 floats per batch

#define TPB 256
#define BPQ 8                            // batches per compute block (quarter of 32)
#define NCOMPUTE (4 * DIM / TPB)         // 4096 compute blocks (4 share a U stripe)
#define NSLABS   (BATCH * C_CH * RES)    // 16384 zero-slab blocks

// ---- packed fp32x2 helpers (sm_10x FFMA2) ----
__device__ __forceinline__ unsigned long long pack2(float lo, float hi) {
    unsigned long long r;
    asm("mov.b64 %0, {%1, %2};" : "=l"(r) : "f"(lo), "f"(hi));
    return r;
}
__device__ __forceinline__ void unpack2(unsigned long long v, float& lo, float& hi) {
    asm("mov.b64 {%0, %1}, %2;" : "=f"(lo), "=f"(hi) : "l"(v));
}
__device__ __forceinline__ unsigned long long fma2(unsigned long long a,
                                                   unsigned long long b,
                                                   unsigned long long c) {
    unsigned long long r;
    asm("fma.rn.f32x2 %0, %1, %2, %3;" : "=l"(r) : "l"(a), "l"(b), "l"(c));
    return r;
}

// Fused kernel:
//   blocks [0, NCOMPUTE)       : GEMM core fill; groups of 4 adjacent blocks share
//                                one U d-stripe (L2 reuse), each covering 8 batches
//   blocks [NCOMPUTE, +NSLABS) : zero the periphery of one (b,c,i) 64x64 slab
__global__ __launch_bounds__(TPB)
void core_part_fused(const float* __restrict__ z,
                     const float* __restrict__ U,
                     const float* __restrict__ L,
                     const float* __restrict__ mu,
                     float* __restrict__ out) {
    const unsigned tid = threadIdx.x;

    if (blockIdx.x >= NCOMPUTE) {
        // ---------------- zero-fill one (b,c,i) slab's periphery ----------------
        const unsigned slab = blockIdx.x - NCOMPUTE;
        const unsigned i = slab & 63;
        const unsigned c = (slab >> 6) & 7;
        const unsigned b = slab >> 9;
        float4* base = reinterpret_cast<float4*>(
            out + (unsigned)(b * BSTRIDE + c * VOL + i * (RES * RES)));
        const float4 zz = make_float4(0.f, 0.f, 0.f, 0.f);

        if (i < POS || i >= POS + CORE) {
            // whole 64x64 slab is periphery: 1024 float4
            #pragma unroll
            for (unsigned idx = tid; idx < 1024; idx += TPB)
                __stcs(&base[idx], zz);
        } else {
            // core-i slab: 32 full periphery rows (512 float4) + k-edges (256 float4)
            #pragma unroll
            for (unsigned idx = tid; idx < 768; idx += TPB) {
                if (idx < 512) {
                    unsigned row = idx >> 4;                 // 0..31
                    unsigned jj = (row < POS) ? row : row + CORE;
                    unsigned col4 = idx & 15;
                    __stcs(&base[jj * 16 + col4], zz);
                } else {
                    unsigned t = idx - 512;                  // 0..255
                    unsigned row = t >> 3;                   // 0..31
                    unsigned j = row + POS;
                    unsigned q = t & 7;
                    unsigned k4 = (q < 4) ? q : q + 8;       // float4 index within row
                    __stcs(&base[j * 16 + k4], zz);
                }
            }
        }
        return;
    }

    // ---------------- GEMM core fill (8 batches per block) ----------------
    const unsigned stripe = blockIdx.x >> 2;               // 0..1023 : d-stripe
    const unsigned bq     = (blockIdx.x & 3) * BPQ;        // batch offset: 0/8/16/24

    __shared__ __align__(16) float a_s[NB * BPQ];          // a_s[n*8 + bl] = L[n]*z[bq+bl, n]

    #pragma unroll
    for (unsigned idx = tid; idx < NB * BPQ; idx += TPB) {
        unsigned n  = idx >> 3;                            // 0..63
        unsigned bl = idx & 7;                             // 0..7
        a_s[idx] = L[n] * z[(bq + bl) * NB + n];
    }
    __syncthreads();

    const unsigned d = stripe * TPB + tid;                 // contiguous per warp

    unsigned long long acc[BPQ / 2];                       // f32x2: local batches (2p, 2p+1)
    #pragma unroll
    for (int p = 0; p < BPQ / 2; p++) acc[p] = 0ull;

    const ulonglong2* a_v = reinterpret_cast<const ulonglong2*>(a_s); // 2 per n

    #pragma unroll 8
    for (unsigned n = 0; n < NB; n++) {
        float u = __ldg(&U[n * (unsigned)DIM + d]);
        unsigned long long u2 = pack2(u, u);
        #pragma unroll
        for (int q = 0; q < 2; q++) {                      // 2 * ulonglong2 = 8 batches
            ulonglong2 av = a_v[n * 2 + q];
            acc[q * 2 + 0] = fma2(av.x, u2, acc[q * 2 + 0]);
            acc[q * 2 + 1] = fma2(av.y, u2, acc[q * 2 + 1]);
        }
    }

    const float m = mu[d];

    const unsigned k = d & 31;
    const unsigned j = (d >> 5) & 31;
    const unsigned i = (d >> 10) & 31;
    const unsigned c = d >> 15;

    const unsigned base = c * VOL
                        + (i + POS) * (RES * RES)
                        + (j + POS) * RES
                        + (k + POS)
                        + bq * (unsigned)BSTRIDE;

    #pragma unroll
    for (int p = 0; p < BPQ / 2; p++) {
        float lo, hi;
        unpack2(acc[p], lo, hi);
        __stcs(&out[base + (unsigned)(2 * p + 0) * BSTRIDE], lo + m);
        __stcs(&out[base + (unsigned)(2 * p + 1) * BSTRIDE], hi + m);
    }
}

extern "C" void kernel_launch(void* const* d_in, const int* in_sizes, int n_in,
                              void* d_out, int out_size) {
    const float* z  = (const float*)d_in[0];   // (32, 64)
    const float* U  = (const float*)d_in[1];   // (64, 262144)
    const float* L  = (const float*)d_in[2];   // (64,)
    const float* mu = (const float*)d_in[3];   // (262144,)
    float* out = (float*)d_out;                // (32, 8, 64, 64, 64)

    core_part_fused<<<NCOMPUTE + NSLABS, TPB>>>(z, U, L, mu, out);
}

// round 6
// speedup vs baseline: 1.0004x; 1.0004x over previous
#include <cuda_runtime.h>
#include <cstdint>

// Problem constants
#define RES    64
#define C_CH   8
#define NB     64
#define CORE   32
#define POS    16                        // (RES-CORE)/2
#define DIM    (CORE*CORE*CORE*C_CH)     // 262144
#define BATCH  32
#define VOL    (RES*RES*RES)             // 262144
#define BSTRIDE (C_CH*VOL)               // 2097152 floats per batch

#define TPB 256
#define BPH 16                           // batches per compute block (half of 32)
#define NCOMPUTE (2 * DIM / TPB)         // 2048 compute blocks
#define NSLABS   (BATCH * C_CH * RES)    // 16384 zero-slab blocks
// total grid = 18432 = 2048 * 9 ; compute role on bid % 9 == 0

// ---- packed fp32x2 helpers (sm_10x FFMA2) ----
__device__ __forceinline__ unsigned long long pack2(float lo, float hi) {
    unsigned long long r;
    asm("mov.b64 %0, {%1, %2};" : "=l"(r) : "f"(lo), "f"(hi));
    return r;
}
__device__ __forceinline__ void unpack2(unsigned long long v, float& lo, float& hi) {
    asm("mov.b64 {%0, %1}, %2;" : "=f"(lo), "=f"(hi) : "l"(v));
}
__device__ __forceinline__ unsigned long long fma2(unsigned long long a,
                                                   unsigned long long b,
                                                   unsigned long long c) {
    unsigned long long r;
    asm("fma.rn.f32x2 %0, %1, %2, %3;" : "=l"(r) : "l"(a), "l"(b), "l"(c));
    return r;
}

// Fused kernel with INTERLEAVED roles:
//   bid % 9 == 0 : GEMM core fill (cidx = bid/9; pair (2t,2t+1) shares U stripe t)
//   otherwise    : zero the periphery of one (b,c,i) 64x64 slab
// Interleaving keeps DRAM-write (zero blocks) and FMA/LDS (compute blocks)
// co-resident in every scheduling wave, overlapping instead of phasing.
__global__ __launch_bounds__(TPB)
void core_part_fused(const float* __restrict__ z,
                     const float* __restrict__ U,
                     const float* __restrict__ L,
                     const float* __restrict__ mu,
                     float* __restrict__ out) {
    const unsigned tid = threadIdx.x;
    const unsigned bid = blockIdx.x;
    const unsigned grp = bid / 9;
    const unsigned rem = bid - grp * 9;

    if (rem != 0) {
        // ---------------- zero-fill one (b,c,i) slab's periphery ----------------
        const unsigned slab = grp * 8 + (rem - 1);         // 0..16383
        const unsigned i = slab & 63;
        const unsigned c = (slab >> 6) & 7;
        const unsigned b = slab >> 9;
        float4* base = reinterpret_cast<float4*>(
            out + (unsigned)(b * BSTRIDE + c * VOL + i * (RES * RES)));
        const float4 zz = make_float4(0.f, 0.f, 0.f, 0.f);

        if (i < POS || i >= POS + CORE) {
            // whole 64x64 slab is periphery: 1024 float4
            #pragma unroll
            for (unsigned idx = tid; idx < 1024; idx += TPB)
                __stcs(&base[idx], zz);
        } else {
            // core-i slab: 32 full periphery rows (512 float4) + k-edges (256 float4)
            #pragma unroll
            for (unsigned idx = tid; idx < 768; idx += TPB) {
                if (idx < 512) {
                    unsigned row = idx >> 4;                 // 0..31
                    unsigned jj = (row < POS) ? row : row + CORE;
                    unsigned col4 = idx & 15;
                    __stcs(&base[jj * 16 + col4], zz);
                } else {
                    unsigned t = idx - 512;                  // 0..255
                    unsigned row = t >> 3;                   // 0..31
                    unsigned j = row + POS;
                    unsigned q = t & 7;
                    unsigned k4 = (q < 4) ? q : q + 8;       // float4 index within row
                    __stcs(&base[j * 16 + k4], zz);
                }
            }
        }
        return;
    }

    // ---------------- GEMM core fill (16 batches per block) ----------------
    const unsigned cidx   = grp;                           // 0..2047
    const unsigned stripe = cidx >> 1;                     // 0..1023 : d-stripe
    const unsigned bhalf  = (cidx & 1) * BPH;              // 0 or 16 : batch offset

    __shared__ __align__(16) float a_s[NB * BPH];          // a_s[n*16+bl] = L[n]*z[bhalf+bl,n]

    #pragma unroll
    for (unsigned idx = tid; idx < NB * BPH; idx += TPB) {
        unsigned n  = idx >> 4;                            // 0..63
        unsigned bl = idx & 15;                            // 0..15
        a_s[idx] = L[n] * z[(bhalf + bl) * NB + n];
    }
    __syncthreads();

    const unsigned d = stripe * TPB + tid;                 // contiguous per warp

    unsigned long long acc[BPH / 2];                       // f32x2: local batches (2p,2p+1)
    #pragma unroll
    for (int p = 0; p < BPH / 2; p++) acc[p] = 0ull;

    const ulonglong2* a_v = reinterpret_cast<const ulonglong2*>(a_s); // 4 per n

    #pragma unroll 8
    for (unsigned n = 0; n < NB; n++) {
        float u = __ldg(&U[n * (unsigned)DIM + d]);
        unsigned long long u2 = pack2(u, u);
        #pragma unroll
        for (int q = 0; q < 4; q++) {                      // 4 * ulonglong2 = 16 batches
            ulonglong2 av = a_v[n * 4 + q];
            acc[q * 2 + 0] = fma2(av.x, u2, acc[q * 2 + 0]);
            acc[q * 2 + 1] = fma2(av.y, u2, acc[q * 2 + 1]);
        }
    }

    const float m = mu[d];

    const unsigned k = d & 31;
    const unsigned j = (d >> 5) & 31;
    const unsigned i = (d >> 10) & 31;
    const unsigned c = d >> 15;

    const unsigned base = c * VOL
                        + (i + POS) * (RES * RES)
                        + (j + POS) * RES
                        + (k + POS)
                        + bhalf * (unsigned)BSTRIDE;

    #pragma unroll
    for (int p = 0; p < BPH / 2; p++) {
        float lo, hi;
        unpack2(acc[p], lo, hi);
        __stcs(&out[base + (unsigned)(2 * p + 0) * BSTRIDE], lo + m);
        __stcs(&out[base + (unsigned)(2 * p + 1) * BSTRIDE], hi + m);
    }
}

extern "C" void kernel_launch(void* const* d_in, const int* in_sizes, int n_in,
                              void* d_out, int out_size) {
    const float* z  = (const float*)d_in[0];   // (32, 64)
    const float* U  = (const float*)d_in[1];   // (64, 262144)
    const float* L  = (const float*)d_in[2];   // (64,)
    const float* mu = (const float*)d_in[3];   // (262144,)
    float* out = (float*)d_out;                // (32, 8, 64, 64, 64)

    core_part_fused<<<NCOMPUTE + NSLABS, TPB>>>(z, U, L, mu, out);
}